// round 4
// baseline (speedup 1.0000x reference)
#include <cuda_runtime.h>

// Gray-Scott residual, vectorized 4 outputs/thread.
// input (20,8,3,256,256) f32 -> outputs f_u, f_v each (20,8,1,252,252) concatenated.
// f_u = Du*lap(u)/dx^2 - u*v^2 + f*(1-u) - du/dt
// f_v = Dv*lap(v)/dx^2 + u*v^2 - (f+k)*v - dv/dt

#define T_DIM 20
#define B_DIM 8
#define HH 256
#define WW 256
#define OH 252
#define OW 252
#define CS (HH * WW)              // 65536
#define TS_ (B_DIM * 3 * CS)      // 1572864
#define OPLANE (OH * OW)          // 63504
#define NOUT (T_DIM * B_DIM * OPLANE)

__device__ __forceinline__ void ld8(const float* __restrict__ p, int row, int col0, float* dst)
{
    const float4 a = *reinterpret_cast<const float4*>(p + row * WW + col0);
    const float4 b = *reinterpret_cast<const float4*>(p + row * WW + col0 + 4);
    dst[0] = a.x; dst[1] = a.y; dst[2] = a.z; dst[3] = a.w;
    dst[4] = b.x; dst[5] = b.y; dst[6] = b.z; dst[7] = b.w;
}

__global__ __launch_bounds__(252) void grayscott_loss_kernel(
    const float* __restrict__ in, float* __restrict__ out)
{
    const int j    = threadIdx.x;                      // 0..62  (group of 4 output cols)
    const int y    = blockIdx.x * 4 + threadIdx.y;     // 0..251 (output row)
    const int tb   = blockIdx.y;                       // 0..159
    const int t    = tb >> 3;
    const int col0 = j * 4;                            // input col base (outputs col0..col0+3 need cols col0..col0+7)

    const float* __restrict__ u = in + (size_t)tb * 3 * CS + CS;   // channel 1
    const float* __restrict__ v = u + CS;                          // channel 2

    const float C1 = 4.0f / 3.0f;
    const float C2 = -1.0f / 12.0f;
    const float INV_DX2 = 40.96f;     // dx = 20/128 exactly
    const float Du = 0.16f, Dv = 0.08f, Ff = 0.06f, FpK = 0.122f;

    float lapu[4], lapv[4], ucv[4], vcv[4], ut[4], vt[4];

    // ---------------- u channel ----------------
    {
        float c[8], rm2[8], rm1[8], rp1[8], rp2[8];
        ld8(u, y + 2, col0, c);
        ld8(u, y,     col0, rm2);
        ld8(u, y + 1, col0, rm1);
        ld8(u, y + 3, col0, rp1);
        ld8(u, y + 4, col0, rp2);
        #pragma unroll
        for (int k = 0; k < 4; k++) {
            const float uc = c[k + 2];
            ucv[k] = uc;
            lapu[k] = (C1 * (c[k + 1] + c[k + 3] + rm1[k + 2] + rp1[k + 2])
                     + C2 * (c[k] + c[k + 4] + rm2[k + 2] + rp2[k + 2])
                     - 5.0f * uc) * INV_DX2;
        }
        float p1[8], p2[8];
        if (t == 0) {
            ld8(u + TS_,     y + 2, col0, p1);
            ld8(u + 2 * TS_, y + 2, col0, p2);
            #pragma unroll
            for (int k = 0; k < 4; k++)
                ut[k] = (-1.5f * ucv[k] + 2.0f * p1[k + 2] - 0.5f * p2[k + 2]) * 20.0f;
        } else if (t == T_DIM - 1) {
            ld8(u - TS_,     y + 2, col0, p1);
            ld8(u - 2 * TS_, y + 2, col0, p2);
            #pragma unroll
            for (int k = 0; k < 4; k++)
                ut[k] = (0.5f * p2[k + 2] - 2.0f * p1[k + 2] + 1.5f * ucv[k]) * 20.0f;
        } else {
            ld8(u + TS_, y + 2, col0, p1);
            ld8(u - TS_, y + 2, col0, p2);
            #pragma unroll
            for (int k = 0; k < 4; k++)
                ut[k] = (p1[k + 2] - p2[k + 2]) * 10.0f;
        }
    }

    // ---------------- v channel ----------------
    {
        float c[8], rm2[8], rm1[8], rp1[8], rp2[8];
        ld8(v, y + 2, col0, c);
        ld8(v, y,     col0, rm2);
        ld8(v, y + 1, col0, rm1);
        ld8(v, y + 3, col0, rp1);
        ld8(v, y + 4, col0, rp2);
        #pragma unroll
        for (int k = 0; k < 4; k++) {
            const float vc = c[k + 2];
            vcv[k] = vc;
            lapv[k] = (C1 * (c[k + 1] + c[k + 3] + rm1[k + 2] + rp1[k + 2])
                     + C2 * (c[k] + c[k + 4] + rm2[k + 2] + rp2[k + 2])
                     - 5.0f * vc) * INV_DX2;
        }
        float p1[8], p2[8];
        if (t == 0) {
            ld8(v + TS_,     y + 2, col0, p1);
            ld8(v + 2 * TS_, y + 2, col0, p2);
            #pragma unroll
            for (int k = 0; k < 4; k++)
                vt[k] = (-1.5f * vcv[k] + 2.0f * p1[k + 2] - 0.5f * p2[k + 2]) * 20.0f;
        } else if (t == T_DIM - 1) {
            ld8(v - TS_,     y + 2, col0, p1);
            ld8(v - 2 * TS_, y + 2, col0, p2);
            #pragma unroll
            for (int k = 0; k < 4; k++)
                vt[k] = (0.5f * p2[k + 2] - 2.0f * p1[k + 2] + 1.5f * vcv[k]) * 20.0f;
        } else {
            ld8(v + TS_, y + 2, col0, p1);
            ld8(v - TS_, y + 2, col0, p2);
            #pragma unroll
            for (int k = 0; k < 4; k++)
                vt[k] = (p1[k + 2] - p2[k + 2]) * 10.0f;
        }
    }

    // ---------------- combine + store ----------------
    float4 fu, fv;
    float fua[4], fva[4];
    #pragma unroll
    for (int k = 0; k < 4; k++) {
        const float uvv = ucv[k] * vcv[k] * vcv[k];
        fua[k] = Du * lapu[k] - uvv + Ff * (1.0f - ucv[k]) - ut[k];
        fva[k] = Dv * lapv[k] + uvv - FpK * vcv[k] - vt[k];
    }
    fu.x = fua[0]; fu.y = fua[1]; fu.z = fua[2]; fu.w = fua[3];
    fv.x = fva[0]; fv.y = fva[1]; fv.z = fva[2]; fv.w = fva[3];

    const size_t o = (size_t)tb * OPLANE + (size_t)y * OW + col0;
    *reinterpret_cast<float4*>(out + o)        = fu;
    *reinterpret_cast<float4*>(out + o + NOUT) = fv;
}

extern "C" void kernel_launch(void* const* d_in, const int* in_sizes, int n_in,
                              void* d_out, int out_size)
{
    const float* in = (const float*)d_in[0];
    float* out = (float*)d_out;
    dim3 block(63, 4, 1);      // 252 threads: 63 col-groups x 4 rows
    dim3 grid(OH / 4, T_DIM * B_DIM, 1);   // 63 row-blocks x 160 (t,b)
    grayscott_loss_kernel<<<grid, block>>>(in, out);
}

// round 5
// speedup vs baseline: 1.0899x; 1.0899x over previous
#include <cuda_runtime.h>

// Gray-Scott residual, 2(y) x 4(x) outputs per thread, aligned LDG.128 + warp-shuffle halos.
// input (20,8,3,256,256) f32 -> outputs f_u, f_v each (20,8,1,252,252) concatenated.

#define T_DIM 20
#define B_DIM 8
#define HH 256
#define WW 256
#define OH 252
#define OW 252
#define CS (HH * WW)              // 65536
#define TS_ (B_DIM * 3 * CS)      // 1572864
#define OPLANE (OH * OW)          // 63504
#define NOUT (T_DIM * B_DIM * OPLANE)

#define C1f (4.0f / 3.0f)
#define C2f (-1.0f / 12.0f)
#define INV_DX2 40.96f

// Full 8-column row: aligned float4 + right-neighbor float4 via shfl (edge lanes load directly).
__device__ __forceinline__ void ldrow8(const float* __restrict__ p, bool edge, float c[8])
{
    const float4 a = *reinterpret_cast<const float4*>(p);
    c[0] = a.x; c[1] = a.y; c[2] = a.z; c[3] = a.w;
    float b0 = __shfl_down_sync(0xffffffffu, a.x, 1);
    float b1 = __shfl_down_sync(0xffffffffu, a.y, 1);
    float b2 = __shfl_down_sync(0xffffffffu, a.z, 1);
    float b3 = __shfl_down_sync(0xffffffffu, a.w, 1);
    if (edge) {
        const float4 e = *reinterpret_cast<const float4*>(p + 4);
        b0 = e.x; b1 = e.y; b2 = e.z; b3 = e.w;
    }
    c[4] = b0; c[5] = b1; c[6] = b2; c[7] = b3;
}

// Center-4 columns (cols col0+2..col0+5): aligned float4, 2 halo floats via shfl.
__device__ __forceinline__ void ldrow4(const float* __restrict__ p, bool edge, float c[4])
{
    const float4 a = *reinterpret_cast<const float4*>(p);
    float b0 = __shfl_down_sync(0xffffffffu, a.x, 1);
    float b1 = __shfl_down_sync(0xffffffffu, a.y, 1);
    if (edge) {
        const float2 e = *reinterpret_cast<const float2*>(p + 4);
        b0 = e.x; b1 = e.y;
    }
    c[0] = a.z; c[1] = a.w; c[2] = b0; c[3] = b1;
}

struct ChanRes {
    float lap0[4], lap1[4], c0[4], c1[4], td0[4], td1[4];
};

__device__ __forceinline__ void do_channel(
    const float* __restrict__ base, int yy0, int col0, bool edge,
    int offA, int offB, float al, float be, float ga, ChanRes& R)
{
    const float* p = base + yy0 * WW + col0;

    float r2[8], r3[8], r0c[4], r1c[4], r4c[4], r5c[4];
    ldrow8(p + 2 * WW, edge, r2);
    ldrow8(p + 3 * WW, edge, r3);
    ldrow4(p + 0 * WW, edge, r0c);
    ldrow4(p + 1 * WW, edge, r1c);
    ldrow4(p + 4 * WW, edge, r4c);
    ldrow4(p + 5 * WW, edge, r5c);

    float A0[4], B0[4], A1[4], B1[4];
    ldrow4(p + offA + 2 * WW, edge, A0);
    ldrow4(p + offB + 2 * WW, edge, B0);
    ldrow4(p + offA + 3 * WW, edge, A1);
    ldrow4(p + offB + 3 * WW, edge, B1);

    #pragma unroll
    for (int k = 0; k < 4; k++) {
        const float c0 = r2[k + 2];
        const float c1 = r3[k + 2];
        R.lap0[k] = (C1f * (r2[k + 1] + r2[k + 3] + r1c[k] + r3[k + 2])
                   + C2f * (r2[k] + r2[k + 4] + r0c[k] + r4c[k])
                   - 5.0f * c0) * INV_DX2;
        R.lap1[k] = (C1f * (r3[k + 1] + r3[k + 3] + r2[k + 2] + r4c[k])
                   + C2f * (r3[k] + r3[k + 4] + r1c[k] + r5c[k])
                   - 5.0f * c1) * INV_DX2;
        R.c0[k] = c0;
        R.c1[k] = c1;
        R.td0[k] = al * c0 + be * A0[k] + ga * B0[k];
        R.td1[k] = al * c1 + be * A1[k] + ga * B1[k];
    }
}

__global__ __launch_bounds__(128) void grayscott_loss_kernel(
    const float* __restrict__ in, float* __restrict__ out)
{
    const int tx   = threadIdx.x;                    // 0..63
    const int ty   = threadIdx.y;                    // 0..1
    const int lane = tx & 31;
    const bool edge = (lane == 31) || (tx == 62);
    const int col0 = min(4 * tx, 248);               // tx==63 duplicates tx==62's tile
    const int yy0  = blockIdx.x * 4 + ty * 2;        // output rows yy0, yy0+1
    const int tb   = blockIdx.y;                     // 0..159
    const int t    = tb >> 3;

    const float* __restrict__ u = in + (size_t)tb * 3 * CS + CS;   // channel 1
    const float* __restrict__ v = u + CS;                          // channel 2

    // Unified time-derivative scheme: td = al*center + be*x[offA] + ga*x[offB]
    int offA, offB;
    float al, be, ga;
    if (t == 0)              { offA =  TS_;  offB =  2 * TS_; al = -30.0f; be =  40.0f; ga = -10.0f; }
    else if (t == T_DIM - 1) { offA = -TS_;  offB = -2 * TS_; al =  30.0f; be = -40.0f; ga =  10.0f; }
    else                     { offA =  TS_;  offB = -TS_;     al =   0.0f; be =  10.0f; ga = -10.0f; }

    ChanRes U, V;
    do_channel(u, yy0, col0, edge, offA, offB, al, be, ga, U);
    do_channel(v, yy0, col0, edge, offA, offB, al, be, ga, V);

    const float Du = 0.16f, Dv = 0.08f, Ff = 0.06f, FpK = 0.122f;

    float4 fu0, fu1, fv0, fv1;
    float* pfu0 = &fu0.x; float* pfu1 = &fu1.x;
    float* pfv0 = &fv0.x; float* pfv1 = &fv1.x;
    #pragma unroll
    for (int k = 0; k < 4; k++) {
        const float uvv0 = U.c0[k] * V.c0[k] * V.c0[k];
        const float uvv1 = U.c1[k] * V.c1[k] * V.c1[k];
        pfu0[k] = Du * U.lap0[k] - uvv0 + Ff * (1.0f - U.c0[k]) - U.td0[k];
        pfu1[k] = Du * U.lap1[k] - uvv1 + Ff * (1.0f - U.c1[k]) - U.td1[k];
        pfv0[k] = Dv * V.lap0[k] + uvv0 - FpK * V.c0[k] - V.td0[k];
        pfv1[k] = Dv * V.lap1[k] + uvv1 - FpK * V.c1[k] - V.td1[k];
    }

    const size_t o = (size_t)tb * OPLANE + (size_t)yy0 * OW + col0;
    *reinterpret_cast<float4*>(out + o)              = fu0;
    *reinterpret_cast<float4*>(out + o + OW)         = fu1;
    *reinterpret_cast<float4*>(out + o + NOUT)       = fv0;
    *reinterpret_cast<float4*>(out + o + NOUT + OW)  = fv1;
}

extern "C" void kernel_launch(void* const* d_in, const int* in_sizes, int n_in,
                              void* d_out, int out_size)
{
    const float* in = (const float*)d_in[0];
    float* out = (float*)d_out;
    dim3 block(64, 2, 1);            // 128 threads, 4 full warps
    dim3 grid(OH / 4, T_DIM * B_DIM, 1);   // 63 x 160
    grayscott_loss_kernel<<<grid, block>>>(in, out);
}

// round 6
// speedup vs baseline: 1.1190x; 1.0267x over previous
#include <cuda_runtime.h>

// Gray-Scott residual, 2(y) x 4(x) outputs/thread, aligned LDG.128 + warp-shuffle halos,
// channel-phased to minimize register pressure (forced 10 CTAs/SM).
// input (20,8,3,256,256) f32 -> outputs f_u, f_v each (20,8,1,252,252) concatenated.

#define T_DIM 20
#define B_DIM 8
#define HH 256
#define WW 256
#define OH 252
#define OW 252
#define CS (HH * WW)              // 65536
#define TS_ (B_DIM * 3 * CS)      // 1572864
#define OPLANE (OH * OW)          // 63504
#define NOUT (T_DIM * B_DIM * OPLANE)

#define C1f (4.0f / 3.0f)
#define C2f (-1.0f / 12.0f)
#define INV_DX2 40.96f

// Full 8-column row: aligned LDG.128 + right-neighbor float4 via shfl (edge lanes load directly).
__device__ __forceinline__ void ldrow8(const float* __restrict__ p, bool edge, float c[8])
{
    const float4 a = *reinterpret_cast<const float4*>(p);
    c[0] = a.x; c[1] = a.y; c[2] = a.z; c[3] = a.w;
    float b0 = __shfl_down_sync(0xffffffffu, a.x, 1);
    float b1 = __shfl_down_sync(0xffffffffu, a.y, 1);
    float b2 = __shfl_down_sync(0xffffffffu, a.z, 1);
    float b3 = __shfl_down_sync(0xffffffffu, a.w, 1);
    if (edge) {
        const float4 e = *reinterpret_cast<const float4*>(p + 4);
        b0 = e.x; b1 = e.y; b2 = e.z; b3 = e.w;
    }
    c[4] = b0; c[5] = b1; c[6] = b2; c[7] = b3;
}

// Center-4 columns (cols col0+2..col0+5): aligned LDG.128, 2 halo floats via shfl.
__device__ __forceinline__ void ldrow4(const float* __restrict__ p, bool edge, float c[4])
{
    const float4 a = *reinterpret_cast<const float4*>(p);
    float b0 = __shfl_down_sync(0xffffffffu, a.x, 1);
    float b1 = __shfl_down_sync(0xffffffffu, a.y, 1);
    if (edge) {
        const float2 e = *reinterpret_cast<const float2*>(p + 4);
        b0 = e.x; b1 = e.y;
    }
    c[0] = a.z; c[1] = a.w; c[2] = b0; c[3] = b1;
}

// Compute lap (scaled), time-derivative, and center values for one channel, one 2x4 tile.
__device__ __forceinline__ void chan_core(
    const float* __restrict__ base, int yy0, int col0, bool edge,
    int offA, int offB, float al, float be, float ga,
    float lap0[4], float lap1[4], float c0[4], float c1[4],
    float td0[4], float td1[4])
{
    const float* p = base + yy0 * WW + col0;

    float r2[8], r3[8], r0c[4], r1c[4], r4c[4], r5c[4];
    ldrow8(p + 2 * WW, edge, r2);
    ldrow8(p + 3 * WW, edge, r3);
    ldrow4(p + 0 * WW, edge, r0c);
    ldrow4(p + 1 * WW, edge, r1c);
    ldrow4(p + 4 * WW, edge, r4c);
    ldrow4(p + 5 * WW, edge, r5c);

    float A0[4], B0[4], A1[4], B1[4];
    ldrow4(p + offA + 2 * WW, edge, A0);
    ldrow4(p + offB + 2 * WW, edge, B0);
    ldrow4(p + offA + 3 * WW, edge, A1);
    ldrow4(p + offB + 3 * WW, edge, B1);

    #pragma unroll
    for (int k = 0; k < 4; k++) {
        const float cc0 = r2[k + 2];
        const float cc1 = r3[k + 2];
        lap0[k] = (C1f * (r2[k + 1] + r2[k + 3] + r1c[k] + r3[k + 2])
                 + C2f * (r2[k] + r2[k + 4] + r0c[k] + r4c[k])
                 - 5.0f * cc0) * INV_DX2;
        lap1[k] = (C1f * (r3[k + 1] + r3[k + 3] + r2[k + 2] + r4c[k])
                 + C2f * (r3[k] + r3[k + 4] + r1c[k] + r5c[k])
                 - 5.0f * cc1) * INV_DX2;
        c0[k] = cc0;
        c1[k] = cc1;
        td0[k] = al * cc0 + be * A0[k] + ga * B0[k];
        td1[k] = al * cc1 + be * A1[k] + ga * B1[k];
    }
}

__global__ __launch_bounds__(128, 10) void grayscott_loss_kernel(
    const float* __restrict__ in, float* __restrict__ out)
{
    const int tx   = threadIdx.x;                    // 0..63
    const int ty   = threadIdx.y;                    // 0..1
    const int lane = tx & 31;
    const bool edge = (lane == 31) || (tx == 62);
    const int col0 = min(4 * tx, 248);               // tx==63 duplicates tx==62 (benign)
    const int yy0  = blockIdx.x * 4 + ty * 2;        // output rows yy0, yy0+1
    const int tb   = blockIdx.y;                     // 0..159
    const int t    = tb >> 3;

    const float* __restrict__ u = in + (size_t)tb * 3 * CS + CS;   // channel 1
    const float* __restrict__ v = u + CS;                          // channel 2

    // time derivative scheme: td = al*center + be*x[offA] + ga*x[offB]
    int offA, offB;
    float al, be, ga;
    if (t == 0)              { offA =  TS_;  offB =  2 * TS_; al = -30.0f; be =  40.0f; ga = -10.0f; }
    else if (t == T_DIM - 1) { offA = -TS_;  offB = -2 * TS_; al =  30.0f; be = -40.0f; ga =  10.0f; }
    else                     { offA =  TS_;  offB = -TS_;     al =   0.0f; be =  10.0f; ga = -10.0f; }

    const float Du = 0.16f, Dv = 0.08f, Ff = 0.06f, FpK = 0.122f;

    // ---- u phase: fold everything into 16 live registers ----
    float pu0[4], pu1[4], uc0[4], uc1[4];
    {
        float lap0[4], lap1[4], c0[4], c1[4], td0[4], td1[4];
        chan_core(u, yy0, col0, edge, offA, offB, al, be, ga,
                  lap0, lap1, c0, c1, td0, td1);
        #pragma unroll
        for (int k = 0; k < 4; k++) {
            pu0[k] = Du * lap0[k] - td0[k] + Ff * (1.0f - c0[k]);
            pu1[k] = Du * lap1[k] - td1[k] + Ff * (1.0f - c1[k]);
            uc0[k] = c0[k];
            uc1[k] = c1[k];
        }
    }

    // ---- v phase: finish both outputs ----
    float4 fu0, fu1, fv0, fv1;
    {
        float lap0[4], lap1[4], c0[4], c1[4], td0[4], td1[4];
        chan_core(v, yy0, col0, edge, offA, offB, al, be, ga,
                  lap0, lap1, c0, c1, td0, td1);
        float* pfu0 = &fu0.x; float* pfu1 = &fu1.x;
        float* pfv0 = &fv0.x; float* pfv1 = &fv1.x;
        #pragma unroll
        for (int k = 0; k < 4; k++) {
            const float uvv0 = uc0[k] * c0[k] * c0[k];
            const float uvv1 = uc1[k] * c1[k] * c1[k];
            pfu0[k] = pu0[k] - uvv0;
            pfu1[k] = pu1[k] - uvv1;
            pfv0[k] = Dv * lap0[k] + uvv0 - FpK * c0[k] - td0[k];
            pfv1[k] = Dv * lap1[k] + uvv1 - FpK * c1[k] - td1[k];
        }
    }

    const size_t o = (size_t)tb * OPLANE + (size_t)yy0 * OW + col0;
    *reinterpret_cast<float4*>(out + o)              = fu0;
    *reinterpret_cast<float4*>(out + o + OW)         = fu1;
    *reinterpret_cast<float4*>(out + o + NOUT)       = fv0;
    *reinterpret_cast<float4*>(out + o + NOUT + OW)  = fv1;
}

extern "C" void kernel_launch(void* const* d_in, const int* in_sizes, int n_in,
                              void* d_out, int out_size)
{
    const float* in = (const float*)d_in[0];
    float* out = (float*)d_out;
    dim3 block(64, 2, 1);                  // 128 threads, 4 full warps
    dim3 grid(OH / 4, T_DIM * B_DIM, 1);   // 63 x 160
    grayscott_loss_kernel<<<grid, block>>>(in, out);
}